// round 16
// baseline (speedup 1.0000x reference)
#include <cuda_runtime.h>
#include <cuda_fp16.h>
#include <math.h>
#include <cstdint>

#define D_MODEL 1024
#define NH 16
#define HD 64
#define SEQL 2048
#define BATCH 4
#define MTOT (BATCH * SEQL)

#define LSCALE 2048.0f
#define INV_LSCALE 4.8828125e-4f

// Scratch (static device globals — allocation-free per harness rules)
// fp16 asymmetric split: LEFT operands stored hi-only, RIGHT hi+lo.
// Weight lo parts are PRE-SCALED by 2048 (f16-subnormal avoidance + f16 acc).
#define QKV_ELEMS ((size_t)BATCH * NH * SEQL * HD)
__device__ __half g_qh[QKV_ELEMS];                       // Q: hi only
__device__ __half g_kh[QKV_ELEMS], g_kl[QKV_ELEMS];      // K: hi + lo (unscaled)
__device__ __half g_vh[QKV_ELEMS], g_vl[QKV_ELEMS];      // V: hi + lo (unscaled)
__device__ __half g_xh[(size_t)MTOT * D_MODEL];          // x: hi only
__device__ __half g_wh[(size_t)4 * D_MODEL * D_MODEL];   // weights hi
__device__ __half g_wl[(size_t)4 * D_MODEL * D_MODEL];   // weights lo x2048
__device__ __half g_oh[(size_t)MTOT * D_MODEL];          // attn out: hi only
__device__ float g_rcos[32 * SEQL];   // [p][s]
__device__ float g_rsin[32 * SEQL];

// ===========================================================================
// helpers
// ===========================================================================
__device__ __forceinline__ uint32_t smem_to_u32(const void* p) {
    uint32_t a;
    asm("{ .reg .u64 t; cvta.to.shared.u64 t, %1; cvt.u32.u64 %0, t; }"
        : "=r"(a) : "l"(p));
    return a;
}

__device__ __forceinline__ void ldm_x4(uint32_t* r, uint32_t addr) {
    asm volatile("ldmatrix.sync.aligned.m8n8.x4.shared.b16 {%0,%1,%2,%3}, [%4];"
                 : "=r"(r[0]), "=r"(r[1]), "=r"(r[2]), "=r"(r[3]) : "r"(addr));
}
__device__ __forceinline__ void ldm_x4_t(uint32_t* r, uint32_t addr) {
    asm volatile("ldmatrix.sync.aligned.m8n8.x4.trans.shared.b16 {%0,%1,%2,%3}, [%4];"
                 : "=r"(r[0]), "=r"(r[1]), "=r"(r[2]), "=r"(r[3]) : "r"(addr));
}

__device__ __forceinline__ void mma_f16(float* c, const uint32_t* a,
                                        const uint32_t* b) {
    asm volatile(
        "mma.sync.aligned.m16n8k16.row.col.f32.f16.f16.f32 "
        "{%0,%1,%2,%3}, {%4,%5,%6,%7}, {%8,%9}, {%0,%1,%2,%3};"
        : "+f"(c[0]), "+f"(c[1]), "+f"(c[2]), "+f"(c[3])
        : "r"(a[0]), "r"(a[1]), "r"(a[2]), "r"(a[3]), "r"(b[0]), "r"(b[1]));
}

__device__ __forceinline__ void mma_f16v(float* c, const uint32_t* a,
                                         uint32_t b0, uint32_t b1) {
    asm volatile(
        "mma.sync.aligned.m16n8k16.row.col.f32.f16.f16.f32 "
        "{%0,%1,%2,%3}, {%4,%5,%6,%7}, {%8,%9}, {%0,%1,%2,%3};"
        : "+f"(c[0]), "+f"(c[1]), "+f"(c[2]), "+f"(c[3])
        : "r"(a[0]), "r"(a[1]), "r"(a[2]), "r"(a[3]), "r"(b0), "r"(b1));
}

// f16-accumulate HMMA (hypothesized full-rate vs half-rate fp32-acc)
__device__ __forceinline__ void mma_f16a(uint32_t* c, const uint32_t* a,
                                         uint32_t b0, uint32_t b1) {
    asm volatile(
        "mma.sync.aligned.m16n8k16.row.col.f16.f16.f16.f16 "
        "{%0,%1}, {%2,%3,%4,%5}, {%6,%7}, {%0,%1};"
        : "+r"(c[0]), "+r"(c[1])
        : "r"(a[0]), "r"(a[1]), "r"(a[2]), "r"(a[3]), "r"(b0), "r"(b1));
}

__device__ __forceinline__ float ex2f(float x) {
    float y;
    asm("ex2.approx.f32 %0, %1;" : "=f"(y) : "f"(x));
    return y;
}

#define CP_ASYNC16(dst, src) \
    asm volatile("cp.async.cg.shared.global [%0], [%1], 16;" \
                 :: "r"(dst), "l"(src) : "memory")
#define CP_COMMIT() asm volatile("cp.async.commit_group;" ::: "memory")
#define CP_WAIT(n)  asm volatile("cp.async.wait_group %0;" :: "n"(n) : "memory")

// pack two floats to fp16x2 (hi), and residuals (lo)
__device__ __forceinline__ uint32_t f2h2(float x, float y) {
    __half2 h = __floats2half2_rn(x, y);
    return *reinterpret_cast<uint32_t*>(&h);
}
__device__ __forceinline__ void pack2_hl(float x, float y,
                                         uint32_t& h, uint32_t& l) {
    __half2 hh = __floats2half2_rn(x, y);
    float2 hf = __half22float2(hh);
    __half2 ll = __floats2half2_rn(x - hf.x, y - hf.y);
    h = *reinterpret_cast<uint32_t*>(&hh);
    l = *reinterpret_cast<uint32_t*>(&ll);
}
// weight variant: lo scaled by 2048
__device__ __forceinline__ void pack2_hl_s(float x, float y,
                                           uint32_t& h, uint32_t& l) {
    __half2 hh = __floats2half2_rn(x, y);
    float2 hf = __half22float2(hh);
    __half2 ll = __floats2half2_rn((x - hf.x) * LSCALE, (y - hf.y) * LSCALE);
    h = *reinterpret_cast<uint32_t*>(&hh);
    l = *reinterpret_cast<uint32_t*>(&ll);
}

// ===========================================================================
// RoPE table init + input/weight pre-split + dummy (ncu slot alignment)
// ===========================================================================
__global__ void rope_init(const int* __restrict__ tp) {
    int i = blockIdx.x * blockDim.x + threadIdx.x;
    int p = i >> 11;
    int s = i & (SEQL - 1);
    float theta = 1.f / powf(10000.f, (2.f * p) * (1.f / 64.f));
    float ang = (float)tp[s] * theta;
    float sn, cs;
    sincosf(ang, &sn, &cs);
    g_rcos[i] = cs;
    g_rsin[i] = sn;
}

#define X_F4   ((size_t)MTOT * D_MODEL / 4)
#define W_F4   ((size_t)D_MODEL * D_MODEL / 4)

__global__ void conv_split(const float* __restrict__ x,
                           const float* __restrict__ wq,
                           const float* __restrict__ wk,
                           const float* __restrict__ wv,
                           const float* __restrict__ wo) {
    size_t i4 = (size_t)blockIdx.x * blockDim.x + threadIdx.x;
    if (i4 < X_F4) {
        float4 v = *reinterpret_cast<const float4*>(x + i4 * 4);
        uint2 h;
        h.x = f2h2(v.x, v.y);
        h.y = f2h2(v.z, v.w);
        *reinterpret_cast<uint2*>(g_xh + i4 * 4) = h;
    } else {
        size_t j = i4 - X_F4;
        int mat = (int)(j >> 18);
        size_t within = j & (W_F4 - 1);
        const float* w = (mat == 0) ? wq : (mat == 1) ? wk
                        : (mat == 2) ? wv : wo;
        size_t dst = (size_t)mat * W_F4 + within;
        float4 v = *reinterpret_cast<const float4*>(w + within * 4);
        uint32_t h0, l0, h1, l1;
        pack2_hl_s(v.x, v.y, h0, l0);
        pack2_hl_s(v.z, v.w, h1, l1);
        *reinterpret_cast<uint2*>(g_wh + dst * 4) = make_uint2(h0, h1);
        *reinterpret_cast<uint2*>(g_wl + dst * 4) = make_uint2(l0, l1);
    }
}

__global__ void dummy_k() {}

// ===========================================================================
// fp16 GEMM: pass 1 (A_h·W_h) fp32-acc, pass 2 (A_h·W_l*2048) f16-acc.
// Warp tile 64x32, 8 warps/CTA (256 thr), BK=32, 3-stage cp.async,
// one barrier per chunk, 64B rows + XOR swizzle.
// mode 0: QKV + RoPE epi (q hi; k,v hi+lo).  mode 3: fp32 out (proj).
// ===========================================================================
#define G2RS 64
#define G2TILE (128 * G2RS)          // 8192
#define G2STG (3 * G2TILE)           // 24576: A_h W_h W_l
#define GEMM2_SMEM (3 * G2STG)       // 73728 (3 stages)
#define NCHUNK (D_MODEL / 32)        // 32

#define SWIZ(row, ch) (((ch) ^ (((row) >> 1) & 3)) << 4)

__global__ __launch_bounds__(256) void gemm_tc2(
    const __half* __restrict__ Ah,
    float* __restrict__ Dout, int mode)
{
    extern __shared__ char smem[];
    uint32_t sb = smem_to_u32(smem);
    int tid = threadIdx.x;
    int wid = tid >> 5, lane = tid & 31;
    int m0 = blockIdx.y * 128;
    int n0 = blockIdx.x * 128;

    int nw, mat = 0, wrow;
    if (mode == 3) { wrow = 3 * D_MODEL + n0; nw = n0; }
    else {
        mat = n0 >> 10;
        nw = n0 & 1023;
        wrow = n0;
    }

    const __half* Ahp = Ah + (size_t)m0 * D_MODEL;
    const __half* Whp = g_wh + (size_t)wrow * D_MODEL;
    const __half* Wlp = g_wl + (size_t)wrow * D_MODEL;

    auto prefetch = [&](int c) {
        uint32_t base = sb + (c % 3) * G2STG;
#pragma unroll
        for (int l = 0; l < 6; l++) {
            int idx = tid + l * 256;         // 0..1535
            int reg = idx >> 9;              // 0..2
            int cc = idx & 511;
            int row = cc >> 2, ch = cc & 3;
            const __half* src =
                (reg == 0) ? Ahp : (reg == 1) ? Whp : Wlp;
            CP_ASYNC16(base + reg * G2TILE + row * G2RS + SWIZ(row, ch),
                       src + (size_t)row * D_MODEL + c * 32 + ch * 8);
        }
        CP_COMMIT();
    };

    float acc[4][4][4];
    uint32_t acc2[4][4][2];
#pragma unroll
    for (int i = 0; i < 4; i++)
#pragma unroll
        for (int j = 0; j < 4; j++) {
#pragma unroll
            for (int k = 0; k < 4; k++) acc[i][j][k] = 0.f;
            acc2[i][j][0] = 0u;
            acc2[i][j][1] = 0u;
        }

    int wm = (wid >> 2) * 64;
    int wn = (wid & 3) * 32;

    int frow = lane & 15;
    int fch = lane >> 4;

    prefetch(0);
    prefetch(1);

    for (int c = 0; c < NCHUNK; c++) {
        if (c < NCHUNK - 2) { CP_WAIT(1); }
        else                { CP_WAIT(0); }
        __syncthreads();
        if (c + 2 < NCHUNK) prefetch(c + 2);

        uint32_t bufb = sb + (c % 3) * G2STG;

#pragma unroll
        for (int kk = 0; kk < 2; kk++) {
            int chunk = kk * 2 + fch;
            uint32_t ah[4][4];
#pragma unroll
            for (int mt = 0; mt < 4; mt++) {
                int row = wm + mt * 16 + frow;
                ldm_x4(ah[mt], bufb + row * G2RS + SWIZ(row, chunk));
            }
            uint32_t bh4[2][4], bl4[2][4];
#pragma unroll
            for (int ntp = 0; ntp < 2; ntp++) {
                int row = wn + ntp * 16 + frow;
                uint32_t bo = bufb + G2TILE + row * G2RS + SWIZ(row, chunk);
                ldm_x4(bh4[ntp], bo);
                ldm_x4(bl4[ntp], bo + G2TILE);
            }
            // pass 1: fp32 acc (16 independent chains)
#pragma unroll
            for (int mt = 0; mt < 4; mt++)
#pragma unroll
                for (int nt = 0; nt < 4; nt++)
                    mma_f16v(acc[mt][nt], ah[mt],
                             bh4[nt >> 1][nt & 1], bh4[nt >> 1][(nt & 1) + 2]);
            // pass 2: f16 acc (hypothesized full-rate)
#pragma unroll
            for (int mt = 0; mt < 4; mt++)
#pragma unroll
                for (int nt = 0; nt < 4; nt++)
                    mma_f16a(acc2[mt][nt], ah[mt],
                             bl4[nt >> 1][nt & 1], bl4[nt >> 1][(nt & 1) + 2]);
        }
    }

    int er = lane >> 2;
    int ec = (lane & 3) * 2;

    if (mode == 3) {
#pragma unroll
        for (int mt = 0; mt < 4; mt++) {
            int m = m0 + wm + mt * 16 + er;
#pragma unroll
            for (int nt = 0; nt < 4; nt++) {
                int col = n0 + wn + nt * 8 + ec;
                float2 lo01 = __half22float2(
                    *reinterpret_cast<__half2*>(&acc2[mt][nt][0]));
                float2 lo23 = __half22float2(
                    *reinterpret_cast<__half2*>(&acc2[mt][nt][1]));
                float2 v0 = make_float2(acc[mt][nt][0] + lo01.x * INV_LSCALE,
                                        acc[mt][nt][1] + lo01.y * INV_LSCALE);
                float2 v1 = make_float2(acc[mt][nt][2] + lo23.x * INV_LSCALE,
                                        acc[mt][nt][3] + lo23.y * INV_LSCALE);
                *reinterpret_cast<float2*>(Dout + (size_t)m * D_MODEL + col) = v0;
                *reinterpret_cast<float2*>(Dout + (size_t)(m + 8) * D_MODEL + col) = v1;
            }
        }
        return;
    }

    // QKV epilogue: merge passes, RoPE; q -> hi only, k/v -> hi + lo
#pragma unroll
    for (int mt = 0; mt < 4; mt++) {
        int m = m0 + wm + mt * 16 + er;
        int bi = m >> 11;
        int s0 = m & (SEQL - 1);
#pragma unroll
        for (int nt = 0; nt < 4; nt++) {
            int col = nw + wn + nt * 8 + ec;
            int h = col >> 6, d = col & 63;
            int p = d >> 1;
            float2 lo01 = __half22float2(
                *reinterpret_cast<__half2*>(&acc2[mt][nt][0]));
            float2 lo23 = __half22float2(
                *reinterpret_cast<__half2*>(&acc2[mt][nt][1]));
            float ce[4];
            ce[0] = acc[mt][nt][0] + lo01.x * INV_LSCALE;
            ce[1] = acc[mt][nt][1] + lo01.y * INV_LSCALE;
            ce[2] = acc[mt][nt][2] + lo23.x * INV_LSCALE;
            ce[3] = acc[mt][nt][3] + lo23.y * INV_LSCALE;
#pragma unroll
            for (int rr = 0; rr < 2; rr++) {
                int s = s0 + rr * 8;
                float e0 = ce[rr * 2];
                float e1 = ce[rr * 2 + 1];
                float v0, v1;
                if (mat != 2) {
                    float cs = g_rcos[p * SEQL + s];
                    float sn = g_rsin[p * SEQL + s];
                    v0 = e0 * cs - e1 * sn;
                    v1 = e0 * sn + e1 * cs;
                } else {
                    v0 = e0; v1 = e1;
                }
                size_t o = (((size_t)(bi * NH + h)) * SEQL + s) * HD + d;
                if (mat == 0) {
                    *reinterpret_cast<uint32_t*>(g_qh + o) = f2h2(v0, v1);
                } else {
                    uint32_t ph, pl;
                    pack2_hl(v0, v1, ph, pl);
                    __half* Dh = (mat == 1) ? g_kh : g_vh;
                    __half* Dl = (mat == 1) ? g_kl : g_vl;
                    *reinterpret_cast<uint32_t*>(Dh + o) = ph;
                    *reinterpret_cast<uint32_t*>(Dl + o) = pl;
                }
            }
        }
    }
}

// ===========================================================================
// fp16 2-pass HMMA flash attention (unchanged from R14 WIN).
// ===========================================================================
#define ARS 144
#define AQH_O 0
#define ASTG(st) (64 * ARS + (st) * 4 * 64 * ARS)
#define AKH_O(st) (ASTG(st))
#define AVH_O(st) (ASTG(st) + 2 * 64 * ARS)
#define ATTN_SMEM (64 * ARS + 2 * 4 * 64 * ARS)   // 82944

#define SC2 0.180336880f   /* (1/8) * log2(e) */

__global__ __launch_bounds__(128) void attn_tc()
{
    extern __shared__ char sm[];
    uint32_t sb = smem_to_u32(sm);
    int tid = threadIdx.x;
    int lane = tid & 31, w = tid >> 5;
    int bh = blockIdx.y;
    int qti = gridDim.x - 1 - blockIdx.x;
    int qm0 = qti * 64;

    size_t base = (size_t)bh * SEQL * HD;

    {
        const __half* q_src = g_qh + base + (size_t)qm0 * HD;
#pragma unroll
        for (int l = 0; l < 4; l++) {
            int idx = tid + l * 128;
            int row = idx >> 3, ch = idx & 7;
            CP_ASYNC16(sb + AQH_O + row * ARS + ch * 16,
                       q_src + row * HD + ch * 8);
        }
        CP_COMMIT();
    }

    const __half* kv_src[4] = { g_kh + base, g_kl + base,
                                g_vh + base, g_vl + base };

    auto kv_prefetch = [&](int kt) {
        int st = kt & 1;
        uint32_t stg = sb + ASTG(st);
#pragma unroll
        for (int l = 0; l < 16; l++) {
            int idx = tid + l * 128;
            int reg = idx >> 9;
            int c = idx & 511;
            int row = c >> 3, ch = c & 7;
            CP_ASYNC16(stg + reg * (64 * ARS) + row * ARS + ch * 16,
                       kv_src[reg] + ((size_t)kt * 64 + row) * HD + ch * 8);
        }
        CP_COMMIT();
    };

    int nkt = qti + 1;
    int nsup = (nkt + 1) >> 1;
    kv_prefetch(0);
    kv_prefetch(1);

    uint32_t qfh[4][4];
    {
        CP_WAIT(2);
        __syncthreads();
        uint32_t a_addr = sb + AQH_O +
                          (w * 16 + (lane & 15)) * ARS + (lane >> 4) * 16;
#pragma unroll
        for (int kk = 0; kk < 4; kk++)
            ldm_x4(qfh[kk], a_addr + kk * 32);
    }

    float o[8][4];
#pragma unroll
    for (int i = 0; i < 8; i++)
#pragma unroll
        for (int j = 0; j < 4; j++) o[i][j] = 0.f;
    float m0 = -1e30f, m1 = -1e30f, l0 = 0.f, l1 = 0.f;

    int er = lane >> 2;
    int ec2 = (lane & 3) * 2;
    int row_g0 = qm0 + w * 16 + er;
    int row_g1 = row_g0 + 8;

    uint32_t kb_row = ((lane >> 4) & 1) * 8 + (lane & 7);
    uint32_t kb_kof = ((lane >> 3) & 1) * 16;
    uint32_t v_key = (lane & 7) + ((lane >> 3) & 1) * 8;
    uint32_t v_dof = ((lane >> 4) & 1) * 16;

    for (int j = 0; j < nsup; j++) {
        int kt0 = 2 * j;
        CP_WAIT(0);
        __syncthreads();

        float sc[16][4];
#pragma unroll
        for (int i = 0; i < 16; i++)
#pragma unroll
            for (int q = 0; q < 4; q++) sc[i][q] = 0.f;

#pragma unroll
        for (int stg = 0; stg < 2; stg++) {
            uint32_t khb = sb + AKH_O(stg);
            float (*scp)[4] = sc + stg * 8;
#pragma unroll
            for (int kk = 0; kk < 4; kk++) {
                uint32_t kb4[4][4], kl4[4][4];
#pragma unroll
                for (int ntp = 0; ntp < 4; ntp++) {
                    uint32_t ka = khb + (ntp * 16 + kb_row) * ARS +
                                  kk * 32 + kb_kof;
                    ldm_x4(kb4[ntp], ka);
                    ldm_x4(kl4[ntp], ka + 64 * ARS);
                }
#pragma unroll
                for (int ntp = 0; ntp < 4; ntp++) {
                    mma_f16(scp[2 * ntp],     qfh[kk], kb4[ntp]);
                    mma_f16(scp[2 * ntp + 1], qfh[kk], kb4[ntp] + 2);
                }
#pragma unroll
                for (int ntp = 0; ntp < 4; ntp++) {
                    mma_f16(scp[2 * ntp],     qfh[kk], kl4[ntp]);
                    mma_f16(scp[2 * ntp + 1], qfh[kk], kl4[ntp] + 2);
                }
            }
        }

        bool needMask = (kt0 + 1) >= qti;
#pragma unroll
        for (int nt = 0; nt < 16; nt++) {
            int c0 = (kt0 + (nt >> 3)) * 64 + (nt & 7) * 8 + ec2;
            if (needMask) {
                sc[nt][0] = (c0     > row_g0) ? -1e30f : sc[nt][0] * SC2;
                sc[nt][1] = (c0 + 1 > row_g0) ? -1e30f : sc[nt][1] * SC2;
                sc[nt][2] = (c0     > row_g1) ? -1e30f : sc[nt][2] * SC2;
                sc[nt][3] = (c0 + 1 > row_g1) ? -1e30f : sc[nt][3] * SC2;
            } else {
                sc[nt][0] *= SC2; sc[nt][1] *= SC2;
                sc[nt][2] *= SC2; sc[nt][3] *= SC2;
            }
        }

        float tm0 = -1e30f, tm1 = -1e30f;
#pragma unroll
        for (int nt = 0; nt < 16; nt++) {
            tm0 = fmaxf(tm0, fmaxf(sc[nt][0], sc[nt][1]));
            tm1 = fmaxf(tm1, fmaxf(sc[nt][2], sc[nt][3]));
        }
        tm0 = fmaxf(tm0, __shfl_xor_sync(0xffffffffu, tm0, 1));
        tm0 = fmaxf(tm0, __shfl_xor_sync(0xffffffffu, tm0, 2));
        tm1 = fmaxf(tm1, __shfl_xor_sync(0xffffffffu, tm1, 1));
        tm1 = fmaxf(tm1, __shfl_xor_sync(0xffffffffu, tm1, 2));
        float mn0 = fmaxf(m0, tm0), mn1 = fmaxf(m1, tm1);
        float cf0 = ex2f(m0 - mn0), cf1 = ex2f(m1 - mn1);
        m0 = mn0; m1 = mn1;

        float rs0 = 0.f, rs1 = 0.f;
#pragma unroll
        for (int nt = 0; nt < 16; nt++) {
            float p0 = ex2f(sc[nt][0] - mn0);
            float p1 = ex2f(sc[nt][1] - mn0);
            float p2 = ex2f(sc[nt][2] - mn1);
            float p3 = ex2f(sc[nt][3] - mn1);
            sc[nt][0] = p0; sc[nt][1] = p1; sc[nt][2] = p2; sc[nt][3] = p3;
            rs0 += p0 + p1;
            rs1 += p2 + p3;
        }
        rs0 += __shfl_xor_sync(0xffffffffu, rs0, 1);
        rs0 += __shfl_xor_sync(0xffffffffu, rs0, 2);
        rs1 += __shfl_xor_sync(0xffffffffu, rs1, 1);
        rs1 += __shfl_xor_sync(0xffffffffu, rs1, 2);
        l0 = l0 * cf0 + rs0;
        l1 = l1 * cf1 + rs1;
#pragma unroll
        for (int ng = 0; ng < 8; ng++) {
            o[ng][0] *= cf0; o[ng][1] *= cf0;
            o[ng][2] *= cf1; o[ng][3] *= cf1;
        }

        bool more = (j + 1 < nsup);
#pragma unroll
        for (int stg = 0; stg < 2; stg++) {
            uint32_t vhb = sb + AVH_O(stg);
            float (*scp)[4] = sc + stg * 8;
#pragma unroll
            for (int kk = 0; kk < 4; kk++) {
                uint32_t ph[4];
                ph[0] = f2h2(scp[2 * kk][0],     scp[2 * kk][1]);
                ph[1] = f2h2(scp[2 * kk][2],     scp[2 * kk][3]);
                ph[2] = f2h2(scp[2 * kk + 1][0], scp[2 * kk + 1][1]);
                ph[3] = f2h2(scp[2 * kk + 1][2], scp[2 * kk + 1][3]);
                uint32_t vh4[4][4], vl4[4][4];
#pragma unroll
                for (int ngp = 0; ngp < 4; ngp++) {
                    uint32_t va = vhb + (kk * 16 + v_key) * ARS +
                                  ngp * 32 + v_dof;
                    ldm_x4_t(vh4[ngp], va);
                    ldm_x4_t(vl4[ngp], va + 64 * ARS);
                }
#pragma unroll
                for (int ngp = 0; ngp < 4; ngp++) {
                    mma_f16(o[2 * ngp],     ph, vh4[ngp]);
                    mma_f16(o[2 * ngp + 1], ph, vh4[ngp] + 2);
                }
#pragma unroll
                for (int ngp = 0; ngp < 4; ngp++) {
                    mma_f16(o[2 * ngp],     ph, vl4[ngp]);
                    mma_f16(o[2 * ngp + 1], ph, vl4[ngp] + 2);
                }
            }
            __syncthreads();
            if (more) kv_prefetch(kt0 + 2 + stg);
        }
    }

    int bi = bh >> 4, h = bh & 15;
    float inv0 = 1.f / l0, inv1 = 1.f / l1;
    int s0 = qm0 + w * 16 + er;
#pragma unroll
    for (int ng = 0; ng < 8; ng++) {
        int d = h * 64 + ng * 8 + ec2;
        size_t off0 = ((size_t)bi * SEQL + s0) * D_MODEL + d;
        size_t off1 = ((size_t)bi * SEQL + s0 + 8) * D_MODEL + d;
        *reinterpret_cast<uint32_t*>(g_oh + off0) =
            f2h2(o[ng][0] * inv0, o[ng][1] * inv0);
        *reinterpret_cast<uint32_t*>(g_oh + off1) =
            f2h2(o[ng][2] * inv1, o[ng][3] * inv1);
    }
}

// ---------------------------------------------------------------------------
extern "C" void kernel_launch(void* const* d_in, const int* in_sizes, int n_in,
                              void* d_out, int out_size)
{
    const float* x  = (const float*)d_in[0];
    const int*   tp = (const int*)d_in[1];
    const float* wq = (const float*)d_in[2];
    const float* wk = (const float*)d_in[3];
    const float* wv = (const float*)d_in[4];
    const float* wo = (const float*)d_in[5];
    float* out = (float*)d_out;

    __half *xh, *oh;
    cudaGetSymbolAddress((void**)&xh, g_xh);
    cudaGetSymbolAddress((void**)&oh, g_oh);

    cudaFuncSetAttribute(gemm_tc2,
                         cudaFuncAttributeMaxDynamicSharedMemorySize,
                         GEMM2_SMEM);
    cudaFuncSetAttribute(attn_tc,
                         cudaFuncAttributeMaxDynamicSharedMemorySize,
                         ATTN_SMEM);

    // #1: RoPE cos/sin table
    rope_init<<<(32 * SEQL) / 256, 256>>>(tp);

    // #2: pre-split x (hi) + weights (hi + lo*2048) to fp16
    conv_split<<<(unsigned)((X_F4 + 4 * W_F4) / 256), 256>>>(x, wq, wk, wv, wo);

    // #3: filler so QKV gemm lands on launch #4 (ncu capture slot)
    dummy_k<<<1, 32>>>();

    // #4: fused QKV projection (pass1 fp32-acc, pass2 f16-acc) + RoPE
    dim3 gqkv(3 * D_MODEL / 128, MTOT / 128);
    gemm_tc2<<<gqkv, 256, GEMM2_SMEM>>>(xh, nullptr, 0);

    // #5: causal flash attention (fp16 2-pass, fp32 acc — unchanged)
    dim3 gattn(SEQL / 64, BATCH * NH);
    attn_tc<<<gattn, 128, ATTN_SMEM>>>();

    // #6: output projection
    dim3 gproj(D_MODEL / 128, MTOT / 128);
    gemm_tc2<<<gproj, 256, GEMM2_SMEM>>>(oh, out, 3);
}

// round 17
// speedup vs baseline: 1.2523x; 1.2523x over previous
#include <cuda_runtime.h>
#include <cuda_fp16.h>
#include <math.h>
#include <cstdint>

#define D_MODEL 1024
#define NH 16
#define HD 64
#define SEQL 2048
#define BATCH 4
#define MTOT (BATCH * SEQL)

// Scratch (static device globals — allocation-free per harness rules)
// fp16 asymmetric split: LEFT operands hi-only; K hi+lo; V hi-only
// (V enters as a convex combination -> plain fp16 rounding suffices).
#define QKV_ELEMS ((size_t)BATCH * NH * SEQL * HD)
__device__ __half g_qh[QKV_ELEMS];                       // Q: hi only
__device__ __half g_kh[QKV_ELEMS], g_kl[QKV_ELEMS];      // K: hi + lo
__device__ __half g_vh[QKV_ELEMS];                       // V: hi only
__device__ __half g_xh[(size_t)MTOT * D_MODEL];          // x: hi only
__device__ __half g_wh[(size_t)4 * D_MODEL * D_MODEL];   // weights hi
__device__ __half g_wl[(size_t)4 * D_MODEL * D_MODEL];   // weights lo
__device__ __half g_oh[(size_t)MTOT * D_MODEL];          // attn out: hi only
__device__ float g_rcos[32 * SEQL];   // [p][s]
__device__ float g_rsin[32 * SEQL];

// ===========================================================================
// helpers
// ===========================================================================
__device__ __forceinline__ uint32_t smem_to_u32(const void* p) {
    uint32_t a;
    asm("{ .reg .u64 t; cvta.to.shared.u64 t, %1; cvt.u32.u64 %0, t; }"
        : "=r"(a) : "l"(p));
    return a;
}

__device__ __forceinline__ void ldm_x4(uint32_t* r, uint32_t addr) {
    asm volatile("ldmatrix.sync.aligned.m8n8.x4.shared.b16 {%0,%1,%2,%3}, [%4];"
                 : "=r"(r[0]), "=r"(r[1]), "=r"(r[2]), "=r"(r[3]) : "r"(addr));
}
__device__ __forceinline__ void ldm_x4_t(uint32_t* r, uint32_t addr) {
    asm volatile("ldmatrix.sync.aligned.m8n8.x4.trans.shared.b16 {%0,%1,%2,%3}, [%4];"
                 : "=r"(r[0]), "=r"(r[1]), "=r"(r[2]), "=r"(r[3]) : "r"(addr));
}

__device__ __forceinline__ void mma_f16(float* c, const uint32_t* a,
                                        const uint32_t* b) {
    asm volatile(
        "mma.sync.aligned.m16n8k16.row.col.f32.f16.f16.f32 "
        "{%0,%1,%2,%3}, {%4,%5,%6,%7}, {%8,%9}, {%0,%1,%2,%3};"
        : "+f"(c[0]), "+f"(c[1]), "+f"(c[2]), "+f"(c[3])
        : "r"(a[0]), "r"(a[1]), "r"(a[2]), "r"(a[3]), "r"(b[0]), "r"(b[1]));
}

__device__ __forceinline__ void mma_f16v(float* c, const uint32_t* a,
                                         uint32_t b0, uint32_t b1) {
    asm volatile(
        "mma.sync.aligned.m16n8k16.row.col.f32.f16.f16.f32 "
        "{%0,%1,%2,%3}, {%4,%5,%6,%7}, {%8,%9}, {%0,%1,%2,%3};"
        : "+f"(c[0]), "+f"(c[1]), "+f"(c[2]), "+f"(c[3])
        : "r"(a[0]), "r"(a[1]), "r"(a[2]), "r"(a[3]), "r"(b0), "r"(b1));
}

__device__ __forceinline__ float ex2f(float x) {
    float y;
    asm("ex2.approx.f32 %0, %1;" : "=f"(y) : "f"(x));
    return y;
}

#define CP_ASYNC16(dst, src) \
    asm volatile("cp.async.cg.shared.global [%0], [%1], 16;" \
                 :: "r"(dst), "l"(src) : "memory")
#define CP_COMMIT() asm volatile("cp.async.commit_group;" ::: "memory")
#define CP_WAIT(n)  asm volatile("cp.async.wait_group %0;" :: "n"(n) : "memory")

// pack two floats to fp16x2 (hi), and residuals (lo)
__device__ __forceinline__ uint32_t f2h2(float x, float y) {
    __half2 h = __floats2half2_rn(x, y);
    return *reinterpret_cast<uint32_t*>(&h);
}
__device__ __forceinline__ void pack2_hl(float x, float y,
                                         uint32_t& h, uint32_t& l) {
    __half2 hh = __floats2half2_rn(x, y);
    float2 hf = __half22float2(hh);
    __half2 ll = __floats2half2_rn(x - hf.x, y - hf.y);
    h = *reinterpret_cast<uint32_t*>(&hh);
    l = *reinterpret_cast<uint32_t*>(&ll);
}

// ===========================================================================
// RoPE table init + input/weight pre-split + dummy (ncu slot alignment)
// ===========================================================================
__global__ void rope_init(const int* __restrict__ tp) {
    int i = blockIdx.x * blockDim.x + threadIdx.x;
    int p = i >> 11;
    int s = i & (SEQL - 1);
    float theta = 1.f / powf(10000.f, (2.f * p) * (1.f / 64.f));
    float ang = (float)tp[s] * theta;
    float sn, cs;
    sincosf(ang, &sn, &cs);
    g_rcos[i] = cs;
    g_rsin[i] = sn;
}

#define X_F4   ((size_t)MTOT * D_MODEL / 4)
#define W_F4   ((size_t)D_MODEL * D_MODEL / 4)

__global__ void conv_split(const float* __restrict__ x,
                           const float* __restrict__ wq,
                           const float* __restrict__ wk,
                           const float* __restrict__ wv,
                           const float* __restrict__ wo) {
    size_t i4 = (size_t)blockIdx.x * blockDim.x + threadIdx.x;
    if (i4 < X_F4) {
        float4 v = *reinterpret_cast<const float4*>(x + i4 * 4);
        uint2 h;
        h.x = f2h2(v.x, v.y);
        h.y = f2h2(v.z, v.w);
        *reinterpret_cast<uint2*>(g_xh + i4 * 4) = h;
    } else {
        size_t j = i4 - X_F4;
        int mat = (int)(j >> 18);
        size_t within = j & (W_F4 - 1);
        const float* w = (mat == 0) ? wq : (mat == 1) ? wk
                        : (mat == 2) ? wv : wo;
        size_t dst = (size_t)mat * W_F4 + within;
        float4 v = *reinterpret_cast<const float4*>(w + within * 4);
        uint32_t h0, l0, h1, l1;
        pack2_hl(v.x, v.y, h0, l0);
        pack2_hl(v.z, v.w, h1, l1);
        *reinterpret_cast<uint2*>(g_wh + dst * 4) = make_uint2(h0, h1);
        *reinterpret_cast<uint2*>(g_wl + dst * 4) = make_uint2(l0, l1);
    }
}

__global__ void dummy_k() {}

// ===========================================================================
// fp16 2-pass HMMA GEMM (R14 WIN config: 8 warps, warp tile 64x32).
// BK=32, 3-stage cp.async, one barrier per chunk, 64B rows + XOR swizzle.
// mode 0: QKV + RoPE epi (q,v hi; k hi+lo).  mode 3: fp32 out (proj).
// ===========================================================================
#define G2RS 64
#define G2TILE (128 * G2RS)          // 8192
#define G2STG (3 * G2TILE)           // 24576: A_h W_h W_l
#define GEMM2_SMEM (3 * G2STG)       // 73728 (3 stages)
#define NCHUNK (D_MODEL / 32)        // 32

#define SWIZ(row, ch) (((ch) ^ (((row) >> 1) & 3)) << 4)

__global__ __launch_bounds__(256) void gemm_tc2(
    const __half* __restrict__ Ah,
    float* __restrict__ Dout, int mode)
{
    extern __shared__ char smem[];
    uint32_t sb = smem_to_u32(smem);
    int tid = threadIdx.x;
    int wid = tid >> 5, lane = tid & 31;
    int m0 = blockIdx.y * 128;
    int n0 = blockIdx.x * 128;

    int nw, mat = 0, wrow;
    if (mode == 3) { wrow = 3 * D_MODEL + n0; nw = n0; }
    else {
        mat = n0 >> 10;
        nw = n0 & 1023;
        wrow = n0;
    }

    const __half* Ahp = Ah + (size_t)m0 * D_MODEL;
    const __half* Whp = g_wh + (size_t)wrow * D_MODEL;
    const __half* Wlp = g_wl + (size_t)wrow * D_MODEL;

    auto prefetch = [&](int c) {
        uint32_t base = sb + (c % 3) * G2STG;
#pragma unroll
        for (int l = 0; l < 6; l++) {
            int idx = tid + l * 256;         // 0..1535
            int reg = idx >> 9;              // 0..2
            int cc = idx & 511;
            int row = cc >> 2, ch = cc & 3;
            const __half* src =
                (reg == 0) ? Ahp : (reg == 1) ? Whp : Wlp;
            CP_ASYNC16(base + reg * G2TILE + row * G2RS + SWIZ(row, ch),
                       src + (size_t)row * D_MODEL + c * 32 + ch * 8);
        }
        CP_COMMIT();
    };

    float acc[4][4][4];
#pragma unroll
    for (int i = 0; i < 4; i++)
#pragma unroll
        for (int j = 0; j < 4; j++)
#pragma unroll
            for (int k = 0; k < 4; k++) acc[i][j][k] = 0.f;

    int wm = (wid >> 2) * 64;
    int wn = (wid & 3) * 32;

    int frow = lane & 15;
    int fch = lane >> 4;

    prefetch(0);
    prefetch(1);

    for (int c = 0; c < NCHUNK; c++) {
        if (c < NCHUNK - 2) { CP_WAIT(1); }
        else                { CP_WAIT(0); }
        __syncthreads();
        if (c + 2 < NCHUNK) prefetch(c + 2);

        uint32_t bufb = sb + (c % 3) * G2STG;

#pragma unroll
        for (int kk = 0; kk < 2; kk++) {
            int chunk = kk * 2 + fch;
            uint32_t ah[4][4];
#pragma unroll
            for (int mt = 0; mt < 4; mt++) {
                int row = wm + mt * 16 + frow;
                ldm_x4(ah[mt], bufb + row * G2RS + SWIZ(row, chunk));
            }
            uint32_t bh4[2][4], bl4[2][4];
#pragma unroll
            for (int ntp = 0; ntp < 2; ntp++) {
                int row = wn + ntp * 16 + frow;
                uint32_t bo = bufb + G2TILE + row * G2RS + SWIZ(row, chunk);
                ldm_x4(bh4[ntp], bo);
                ldm_x4(bl4[ntp], bo + G2TILE);
            }
            // 2 passes, pass-major (16 independent chains each)
#pragma unroll
            for (int mt = 0; mt < 4; mt++)
#pragma unroll
                for (int nt = 0; nt < 4; nt++)
                    mma_f16v(acc[mt][nt], ah[mt],
                             bh4[nt >> 1][nt & 1], bh4[nt >> 1][(nt & 1) + 2]);
#pragma unroll
            for (int mt = 0; mt < 4; mt++)
#pragma unroll
                for (int nt = 0; nt < 4; nt++)
                    mma_f16v(acc[mt][nt], ah[mt],
                             bl4[nt >> 1][nt & 1], bl4[nt >> 1][(nt & 1) + 2]);
        }
    }

    int er = lane >> 2;
    int ec = (lane & 3) * 2;

    if (mode == 3) {
#pragma unroll
        for (int mt = 0; mt < 4; mt++) {
            int m = m0 + wm + mt * 16 + er;
#pragma unroll
            for (int nt = 0; nt < 4; nt++) {
                int col = n0 + wn + nt * 8 + ec;
                float2 v0 = make_float2(acc[mt][nt][0], acc[mt][nt][1]);
                float2 v1 = make_float2(acc[mt][nt][2], acc[mt][nt][3]);
                *reinterpret_cast<float2*>(Dout + (size_t)m * D_MODEL + col) = v0;
                *reinterpret_cast<float2*>(Dout + (size_t)(m + 8) * D_MODEL + col) = v1;
            }
        }
        return;
    }

    // QKV epilogue: RoPE; q,v -> hi only, k -> hi + lo
#pragma unroll
    for (int mt = 0; mt < 4; mt++) {
        int m = m0 + wm + mt * 16 + er;
        int bi = m >> 11;
        int s0 = m & (SEQL - 1);
#pragma unroll
        for (int nt = 0; nt < 4; nt++) {
            int col = nw + wn + nt * 8 + ec;
            int h = col >> 6, d = col & 63;
            int p = d >> 1;
#pragma unroll
            for (int rr = 0; rr < 2; rr++) {
                int s = s0 + rr * 8;
                float e0 = acc[mt][nt][rr * 2];
                float e1 = acc[mt][nt][rr * 2 + 1];
                float v0, v1;
                if (mat != 2) {
                    float cs = g_rcos[p * SEQL + s];
                    float sn = g_rsin[p * SEQL + s];
                    v0 = e0 * cs - e1 * sn;
                    v1 = e0 * sn + e1 * cs;
                } else {
                    v0 = e0; v1 = e1;
                }
                size_t o = (((size_t)(bi * NH + h)) * SEQL + s) * HD + d;
                if (mat == 0) {
                    *reinterpret_cast<uint32_t*>(g_qh + o) = f2h2(v0, v1);
                } else if (mat == 2) {
                    *reinterpret_cast<uint32_t*>(g_vh + o) = f2h2(v0, v1);
                } else {
                    uint32_t ph, pl;
                    pack2_hl(v0, v1, ph, pl);
                    *reinterpret_cast<uint32_t*>(g_kh + o) = ph;
                    *reinterpret_cast<uint32_t*>(g_kl + o) = pl;
                }
            }
        }
    }
}

// ===========================================================================
// fp16 HMMA flash attention: QK 2-pass (q_h·k_h + q_h·k_l), PV 1-pass
// (p_h·v_h — V is a convex combination, fp16 rounding suffices).
// Super-tiled (1 softmax / 128 keys). CTA: 64 q-rows, 4 warps.
// Smem: Q_h + 2 stages x {K_h, K_l, V_h} = 64.5 KB.
// ===========================================================================
#define ARS 144
#define AQH_O 0
#define ASTG(st) (64 * ARS + (st) * 3 * 64 * ARS)
#define AKH_O(st) (ASTG(st))
#define AVH_O(st) (ASTG(st) + 2 * 64 * ARS)
#define ATTN_SMEM (64 * ARS + 2 * 3 * 64 * ARS)   // 64512

#define SC2 0.180336880f   /* (1/8) * log2(e) */

__global__ __launch_bounds__(128) void attn_tc()
{
    extern __shared__ char sm[];
    uint32_t sb = smem_to_u32(sm);
    int tid = threadIdx.x;
    int lane = tid & 31, w = tid >> 5;
    int bh = blockIdx.y;
    int qti = gridDim.x - 1 - blockIdx.x;
    int qm0 = qti * 64;

    size_t base = (size_t)bh * SEQL * HD;

    {
        const __half* q_src = g_qh + base + (size_t)qm0 * HD;
#pragma unroll
        for (int l = 0; l < 4; l++) {
            int idx = tid + l * 128;
            int row = idx >> 3, ch = idx & 7;
            CP_ASYNC16(sb + AQH_O + row * ARS + ch * 16,
                       q_src + row * HD + ch * 8);
        }
        CP_COMMIT();
    }

    const __half* kv_src[3] = { g_kh + base, g_kl + base, g_vh + base };

    auto kv_prefetch = [&](int kt) {
        int st = kt & 1;
        uint32_t stg = sb + ASTG(st);
#pragma unroll
        for (int l = 0; l < 12; l++) {
            int idx = tid + l * 128;       // 0..1535
            int reg = idx >> 9;            // 0..2
            int c = idx & 511;
            int row = c >> 3, ch = c & 7;
            CP_ASYNC16(stg + reg * (64 * ARS) + row * ARS + ch * 16,
                       kv_src[reg] + ((size_t)kt * 64 + row) * HD + ch * 8);
        }
        CP_COMMIT();
    };

    int nkt = qti + 1;
    int nsup = (nkt + 1) >> 1;
    kv_prefetch(0);
    kv_prefetch(1);

    uint32_t qfh[4][4];
    {
        CP_WAIT(2);
        __syncthreads();
        uint32_t a_addr = sb + AQH_O +
                          (w * 16 + (lane & 15)) * ARS + (lane >> 4) * 16;
#pragma unroll
        for (int kk = 0; kk < 4; kk++)
            ldm_x4(qfh[kk], a_addr + kk * 32);
    }

    float o[8][4];
#pragma unroll
    for (int i = 0; i < 8; i++)
#pragma unroll
        for (int j = 0; j < 4; j++) o[i][j] = 0.f;
    float m0 = -1e30f, m1 = -1e30f, l0 = 0.f, l1 = 0.f;

    int er = lane >> 2;
    int ec2 = (lane & 3) * 2;
    int row_g0 = qm0 + w * 16 + er;
    int row_g1 = row_g0 + 8;

    uint32_t kb_row = ((lane >> 4) & 1) * 8 + (lane & 7);
    uint32_t kb_kof = ((lane >> 3) & 1) * 16;
    uint32_t v_key = (lane & 7) + ((lane >> 3) & 1) * 8;
    uint32_t v_dof = ((lane >> 4) & 1) * 16;

    for (int j = 0; j < nsup; j++) {
        int kt0 = 2 * j;
        CP_WAIT(0);
        __syncthreads();

        float sc[16][4];
#pragma unroll
        for (int i = 0; i < 16; i++)
#pragma unroll
            for (int q = 0; q < 4; q++) sc[i][q] = 0.f;

#pragma unroll
        for (int stg = 0; stg < 2; stg++) {
            uint32_t khb = sb + AKH_O(stg);
            float (*scp)[4] = sc + stg * 8;
#pragma unroll
            for (int kk = 0; kk < 4; kk++) {
                uint32_t kb4[4][4], kl4[4][4];
#pragma unroll
                for (int ntp = 0; ntp < 4; ntp++) {
                    uint32_t ka = khb + (ntp * 16 + kb_row) * ARS +
                                  kk * 32 + kb_kof;
                    ldm_x4(kb4[ntp], ka);
                    ldm_x4(kl4[ntp], ka + 64 * ARS);
                }
#pragma unroll
                for (int ntp = 0; ntp < 4; ntp++) {
                    mma_f16(scp[2 * ntp],     qfh[kk], kb4[ntp]);
                    mma_f16(scp[2 * ntp + 1], qfh[kk], kb4[ntp] + 2);
                }
#pragma unroll
                for (int ntp = 0; ntp < 4; ntp++) {
                    mma_f16(scp[2 * ntp],     qfh[kk], kl4[ntp]);
                    mma_f16(scp[2 * ntp + 1], qfh[kk], kl4[ntp] + 2);
                }
            }
        }

        bool needMask = (kt0 + 1) >= qti;
#pragma unroll
        for (int nt = 0; nt < 16; nt++) {
            int c0 = (kt0 + (nt >> 3)) * 64 + (nt & 7) * 8 + ec2;
            if (needMask) {
                sc[nt][0] = (c0     > row_g0) ? -1e30f : sc[nt][0] * SC2;
                sc[nt][1] = (c0 + 1 > row_g0) ? -1e30f : sc[nt][1] * SC2;
                sc[nt][2] = (c0     > row_g1) ? -1e30f : sc[nt][2] * SC2;
                sc[nt][3] = (c0 + 1 > row_g1) ? -1e30f : sc[nt][3] * SC2;
            } else {
                sc[nt][0] *= SC2; sc[nt][1] *= SC2;
                sc[nt][2] *= SC2; sc[nt][3] *= SC2;
            }
        }

        float tm0 = -1e30f, tm1 = -1e30f;
#pragma unroll
        for (int nt = 0; nt < 16; nt++) {
            tm0 = fmaxf(tm0, fmaxf(sc[nt][0], sc[nt][1]));
            tm1 = fmaxf(tm1, fmaxf(sc[nt][2], sc[nt][3]));
        }
        tm0 = fmaxf(tm0, __shfl_xor_sync(0xffffffffu, tm0, 1));
        tm0 = fmaxf(tm0, __shfl_xor_sync(0xffffffffu, tm0, 2));
        tm1 = fmaxf(tm1, __shfl_xor_sync(0xffffffffu, tm1, 1));
        tm1 = fmaxf(tm1, __shfl_xor_sync(0xffffffffu, tm1, 2));
        float mn0 = fmaxf(m0, tm0), mn1 = fmaxf(m1, tm1);
        float cf0 = ex2f(m0 - mn0), cf1 = ex2f(m1 - mn1);
        m0 = mn0; m1 = mn1;

        float rs0 = 0.f, rs1 = 0.f;
#pragma unroll
        for (int nt = 0; nt < 16; nt++) {
            float p0 = ex2f(sc[nt][0] - mn0);
            float p1 = ex2f(sc[nt][1] - mn0);
            float p2 = ex2f(sc[nt][2] - mn1);
            float p3 = ex2f(sc[nt][3] - mn1);
            sc[nt][0] = p0; sc[nt][1] = p1; sc[nt][2] = p2; sc[nt][3] = p3;
            rs0 += p0 + p1;
            rs1 += p2 + p3;
        }
        rs0 += __shfl_xor_sync(0xffffffffu, rs0, 1);
        rs0 += __shfl_xor_sync(0xffffffffu, rs0, 2);
        rs1 += __shfl_xor_sync(0xffffffffu, rs1, 1);
        rs1 += __shfl_xor_sync(0xffffffffu, rs1, 2);
        l0 = l0 * cf0 + rs0;
        l1 = l1 * cf1 + rs1;
#pragma unroll
        for (int ng = 0; ng < 8; ng++) {
            o[ng][0] *= cf0; o[ng][1] *= cf0;
            o[ng][2] *= cf1; o[ng][3] *= cf1;
        }

        bool more = (j + 1 < nsup);
#pragma unroll
        for (int stg = 0; stg < 2; stg++) {
            uint32_t vhb = sb + AVH_O(stg);
            float (*scp)[4] = sc + stg * 8;
#pragma unroll
            for (int kk = 0; kk < 4; kk++) {
                uint32_t ph[4];
                ph[0] = f2h2(scp[2 * kk][0],     scp[2 * kk][1]);
                ph[1] = f2h2(scp[2 * kk][2],     scp[2 * kk][3]);
                ph[2] = f2h2(scp[2 * kk + 1][0], scp[2 * kk + 1][1]);
                ph[3] = f2h2(scp[2 * kk + 1][2], scp[2 * kk + 1][3]);
                uint32_t vh4[4][4];
#pragma unroll
                for (int ngp = 0; ngp < 4; ngp++) {
                    uint32_t va = vhb + (kk * 16 + v_key) * ARS +
                                  ngp * 32 + v_dof;
                    ldm_x4_t(vh4[ngp], va);
                }
                // PV single pass (p_h · v_h), pass-major
#pragma unroll
                for (int ngp = 0; ngp < 4; ngp++) {
                    mma_f16(o[2 * ngp],     ph, vh4[ngp]);
                    mma_f16(o[2 * ngp + 1], ph, vh4[ngp] + 2);
                }
            }
            __syncthreads();
            if (more) kv_prefetch(kt0 + 2 + stg);
        }
    }

    int bi = bh >> 4, h = bh & 15;
    float inv0 = 1.f / l0, inv1 = 1.f / l1;
    int s0 = qm0 + w * 16 + er;
#pragma unroll
    for (int ng = 0; ng < 8; ng++) {
        int d = h * 64 + ng * 8 + ec2;
        size_t off0 = ((size_t)bi * SEQL + s0) * D_MODEL + d;
        size_t off1 = ((size_t)bi * SEQL + s0 + 8) * D_MODEL + d;
        *reinterpret_cast<uint32_t*>(g_oh + off0) =
            f2h2(o[ng][0] * inv0, o[ng][1] * inv0);
        *reinterpret_cast<uint32_t*>(g_oh + off1) =
            f2h2(o[ng][2] * inv1, o[ng][3] * inv1);
    }
}

// ---------------------------------------------------------------------------
extern "C" void kernel_launch(void* const* d_in, const int* in_sizes, int n_in,
                              void* d_out, int out_size)
{
    const float* x  = (const float*)d_in[0];
    const int*   tp = (const int*)d_in[1];
    const float* wq = (const float*)d_in[2];
    const float* wk = (const float*)d_in[3];
    const float* wv = (const float*)d_in[4];
    const float* wo = (const float*)d_in[5];
    float* out = (float*)d_out;

    __half *xh, *oh;
    cudaGetSymbolAddress((void**)&xh, g_xh);
    cudaGetSymbolAddress((void**)&oh, g_oh);

    cudaFuncSetAttribute(gemm_tc2,
                         cudaFuncAttributeMaxDynamicSharedMemorySize,
                         GEMM2_SMEM);
    cudaFuncSetAttribute(attn_tc,
                         cudaFuncAttributeMaxDynamicSharedMemorySize,
                         ATTN_SMEM);

    // #1: RoPE cos/sin table
    rope_init<<<(32 * SEQL) / 256, 256>>>(tp);

    // #2: pre-split x (hi) + weights (hi+lo) to fp16
    conv_split<<<(unsigned)((X_F4 + 4 * W_F4) / 256), 256>>>(x, wq, wk, wv, wo);

    // #3: filler so QKV gemm lands on launch #4 (ncu capture slot)
    dummy_k<<<1, 32>>>();

    // #4: fused QKV projection (fp16 2-pass, R14 config) + RoPE
    dim3 gqkv(3 * D_MODEL / 128, MTOT / 128);
    gemm_tc2<<<gqkv, 256, GEMM2_SMEM>>>(xh, nullptr, 0);

    // #5: causal flash attention (QK 2-pass, PV 1-pass)
    dim3 gattn(SEQL / 64, BATCH * NH);
    attn_tc<<<gattn, 128, ATTN_SMEM>>>();

    // #6: output projection
    dim3 gproj(D_MODEL / 128, MTOT / 128);
    gemm_tc2<<<gproj, 256, GEMM2_SMEM>>>(oh, out, 3);
}